// round 6
// baseline (speedup 1.0000x reference)
#include <cuda_runtime.h>
#include <cstdint>

#define BB 4
#define NN 1024
#define CC 1024
#define HH 16
#define HDIM 64

typedef unsigned long long ull;

// ---------------- scratch ----------------
static constexpr size_t OFF_Q   = 0;
static constexpr size_t OFF_K   = OFF_Q + (size_t)BB*HH*NN*HDIM;
static constexpr size_t OFF_VT  = OFF_K + (size_t)BB*HH*NN*HDIM;
static constexpr size_t OFF_MID = OFF_VT + (size_t)BB*HH*NN*HDIM;   // midT[b][c][n]
static constexpr size_t OFF_S   = OFF_MID + (size_t)BB*NN*CC;
static constexpr size_t SCRATCH_TOTAL = OFF_S + (size_t)BB*HH*NN*NN;
__device__ float g_scratch[SCRATCH_TOTAL];

// ---------------- f32x2 helpers ----------------
__device__ __forceinline__ ull splat2(float v) {
  ull r; asm("mov.b64 %0, {%1,%1};" : "=l"(r) : "f"(v)); return r;
}
__device__ __forceinline__ void fma2(ull& d, ull a, ull b) {
  asm("fma.rn.f32x2 %0, %1, %2, %0;" : "+l"(d) : "l"(a), "l"(b));
}
__device__ __forceinline__ float lo32(ull u) { return __uint_as_float((unsigned)u); }
__device__ __forceinline__ float hi32(ull u) { return __uint_as_float((unsigned)(u >> 32)); }

// =========================================================================
// g3_gemm: C[256 rows, 128 cols] tile; thread = 16 rows (8 fma2-pairs) x 8 cols.
// A,B K-major fp32 (or A from midT[b][c][n] when ATRANS=1).
// EPI: 0 plain->O0 (s), 1 qkv scatter (q*scale,k,vT,+bias), 3 proj+bias->O0
// =========================================================================
template <int EPI, int ATRANS>
__global__ __launch_bounds__(256, 1) void g3_gemm(
    const float* __restrict__ Ag, const float* __restrict__ Bg,
    int lda, int ldb, int K, size_t batchA, size_t batchB,
    const float* __restrict__ bias,
    float* __restrict__ O0, float* __restrict__ O1, float* __restrict__ O2,
    int ldo, size_t batchO) {
  constexpr int SRA = 260;   // floats per k-row (256 + pad), mult of 4
  constexpr int SRB = 132;   // 128 + pad
  extern __shared__ float sm[];
  float* AsB = sm;                     // [2][16*SRA]
  float* BsB = sm + 2 * 16 * SRA;      // [2][16*SRB]

  const int tid = threadIdx.x;
  const int ty = tid >> 4, tx = tid & 15;
  const int r0 = ty * 16;
  const int rb = blockIdx.y * 256, ob = blockIdx.x * 128, z = blockIdx.z;

  const float* ABase;
  if (ATRANS) ABase = Ag + ((size_t)(rb >> 10) << 20) + (rb & 1023);
  else        ABase = Ag + (size_t)z * batchA + (size_t)rb * lda;
  const float* BBase = Bg + (size_t)z * batchB + (size_t)ob * ldb;

  ull acc[8][2][4];
#pragma unroll
  for (int p = 0; p < 8; p++)
#pragma unroll
    for (int cg = 0; cg < 2; cg++)
#pragma unroll
      for (int j = 0; j < 4; j++) acc[p][cg][j] = 0ULL;

  float4 pa[4], pb[2];

  auto loadA = [&](int k0) {
    if (ATRANS) {
#pragma unroll
      for (int i = 0; i < 4; i++) {
        int f = tid + 256 * i;
        int kk = f >> 6, rr = (f & 63) << 2;
        pa[i] = __ldg((const float4*)(ABase + (size_t)(k0 + kk) * 1024 + rr));
      }
    } else {
#pragma unroll
      for (int i = 0; i < 4; i++) {
        int f = tid + 256 * i;
        int rr = f >> 2, kq = (f & 3) << 2;
        pa[i] = __ldg((const float4*)(ABase + (size_t)rr * lda + k0 + kq));
      }
    }
  };
  auto loadB = [&](int k0) {
#pragma unroll
    for (int i = 0; i < 2; i++) {
      int f = tid + 256 * i;
      int rr = f >> 2, kq = (f & 3) << 2;
      pb[i] = __ldg((const float4*)(BBase + (size_t)rr * ldb + k0 + kq));
    }
  };
  auto stage = [&](int s) {
    float* As = AsB + s * 16 * SRA;
    float* Bs = BsB + s * 16 * SRB;
    if (ATRANS) {
#pragma unroll
      for (int i = 0; i < 4; i++) {
        int f = tid + 256 * i;
        int kk = f >> 6, rr = (f & 63) << 2;
        *(float4*)&As[kk * SRA + rr] = pa[i];
      }
    } else {
#pragma unroll
      for (int i = 0; i < 4; i++) {
        int f = tid + 256 * i;
        int rr = f >> 2, kq = (f & 3) << 2;
        As[(kq + 0) * SRA + rr] = pa[i].x; As[(kq + 1) * SRA + rr] = pa[i].y;
        As[(kq + 2) * SRA + rr] = pa[i].z; As[(kq + 3) * SRA + rr] = pa[i].w;
      }
    }
#pragma unroll
    for (int i = 0; i < 2; i++) {
      int f = tid + 256 * i;
      int rr = f >> 2, kq = (f & 3) << 2;
      Bs[(kq + 0) * SRB + rr] = pb[i].x; Bs[(kq + 1) * SRB + rr] = pb[i].y;
      Bs[(kq + 2) * SRB + rr] = pb[i].z; Bs[(kq + 3) * SRB + rr] = pb[i].w;
    }
  };

  loadA(0); loadB(0);
  stage(0);
  __syncthreads();

  const int KT = K >> 4;
  int s = 0;
  for (int kt = 0; kt < KT; kt++) {
    if (kt + 1 < KT) { loadA((kt + 1) << 4); loadB((kt + 1) << 4); }
    const float* As = AsB + s * 16 * SRA;
    const float* Bs = BsB + s * 16 * SRB;
#pragma unroll
    for (int kk = 0; kk < 16; kk++) {
      const float* ar = As + kk * SRA + r0;
      ulonglong2 u0 = *(const ulonglong2*)ar;
      ulonglong2 u1 = *(const ulonglong2*)(ar + 4);
      ulonglong2 u2 = *(const ulonglong2*)(ar + 8);
      ulonglong2 u3 = *(const ulonglong2*)(ar + 12);
      ull ap[8] = {u0.x, u0.y, u1.x, u1.y, u2.x, u2.y, u3.x, u3.y};
      const float* br = Bs + kk * SRB + tx * 4;
#pragma unroll
      for (int cg = 0; cg < 2; cg++) {
        float4 bf = *(const float4*)(br + cg * 64);
        float bv[4] = {bf.x, bf.y, bf.z, bf.w};
#pragma unroll
        for (int j = 0; j < 4; j++) {
          ull bsp = splat2(bv[j]);
#pragma unroll
          for (int p = 0; p < 8; p++) fma2(acc[p][cg][j], ap[p], bsp);
        }
      }
    }
    if (kt + 1 < KT) {
      stage(s ^ 1);
      __syncthreads();
    }
    s ^= 1;
  }

  // ---- epilogue ----
#pragma unroll
  for (int cg = 0; cg < 2; cg++) {
    const int c0 = ob + cg * 64 + tx * 4;
    float4 bi = make_float4(0.f, 0.f, 0.f, 0.f);
    if (EPI == 1 || EPI == 3) bi = __ldg((const float4*)(bias + c0));
    if (EPI == 1) {
      const int which = c0 >> 10, h = (c0 >> 6) & 15, d0 = c0 & 63;
      const float bv[4] = {bi.x, bi.y, bi.z, bi.w};
#pragma unroll
      for (int p = 0; p < 8; p++) {
        const int r = rb + r0 + 2 * p;
        const int bcb = r >> 10, n = r & 1023;
        float lo[4], hi[4];
#pragma unroll
        for (int j = 0; j < 4; j++) { lo[j] = lo32(acc[p][cg][j]); hi[j] = hi32(acc[p][cg][j]); }
        if (which == 2) {
#pragma unroll
          for (int j = 0; j < 4; j++)
            *(float2*)(O2 + ((((size_t)bcb * HH + h) * HDIM + d0 + j) << 10) + n) =
                make_float2(lo[j] + bv[j], hi[j] + bv[j]);
        } else {
          float* dst = (which == 0) ? O0 : O1;
          const float sc = (which == 0) ? 0.125f : 1.0f;
          float* p0 = dst + (((size_t)bcb * HH + h) * NN + n) * HDIM + d0;
          *(float4*)p0 = make_float4((lo[0] + bv[0]) * sc, (lo[1] + bv[1]) * sc,
                                     (lo[2] + bv[2]) * sc, (lo[3] + bv[3]) * sc);
          *(float4*)(p0 + HDIM) = make_float4((hi[0] + bv[0]) * sc, (hi[1] + bv[1]) * sc,
                                              (hi[2] + bv[2]) * sc, (hi[3] + bv[3]) * sc);
        }
      }
    } else {
#pragma unroll
      for (int p = 0; p < 8; p++) {
        const int r = rb + r0 + 2 * p;
        float lo[4], hi[4];
#pragma unroll
        for (int j = 0; j < 4; j++) { lo[j] = lo32(acc[p][cg][j]); hi[j] = hi32(acc[p][cg][j]); }
        float* p0 = O0 + (size_t)z * batchO + (size_t)r * ldo + c0;
        if (EPI == 3) {
          *(float4*)p0 = make_float4(lo[0] + bi.x, lo[1] + bi.y, lo[2] + bi.z, lo[3] + bi.w);
          *(float4*)(p0 + ldo) = make_float4(hi[0] + bi.x, hi[1] + bi.y, hi[2] + bi.z, hi[3] + bi.w);
        } else {
          *(float4*)p0 = make_float4(lo[0], lo[1], lo[2], lo[3]);
          *(float4*)(p0 + ldo) = make_float4(hi[0], hi[1], hi[2], hi[3]);
        }
      }
    }
  }
}

// =========================================================================
// g3_av: midT[b][g*64+d][n] = sum_m vT[b,g][d][m] * attn[b,g][n][m]
// M=64 (d), N=512-tile (n), K=1024 (m). Thread = 8 rows (4 pairs) x 16 cols.
// A-frag loads are full-warp broadcasts.
// =========================================================================
__global__ __launch_bounds__(256, 1) void g3_av(
    const float* __restrict__ attn, const float* __restrict__ vT,
    float* __restrict__ midT) {
  constexpr int SRA = 68;    // 64 + pad
  constexpr int SRB = 516;   // 512 + pad
  extern __shared__ float sm[];
  float* AsB = sm;                    // [2][16*SRA]
  float* BsB = sm + 2 * 16 * SRA;     // [2][16*SRB]

  const int tid = threadIdx.x;
  const int ty = tid >> 5, tx = tid & 31;   // 8 x 32
  const int d0 = ty * 8;
  const int nb = blockIdx.x * 512, bg = blockIdx.z;
  const float* Ab = vT + ((size_t)bg << 16);          // [64][1024]
  const float* Bb = attn + ((size_t)bg << 20) + (size_t)nb * 1024;

  ull acc[4][4][4];
#pragma unroll
  for (int p = 0; p < 4; p++)
#pragma unroll
    for (int cg = 0; cg < 4; cg++)
#pragma unroll
      for (int j = 0; j < 4; j++) acc[p][cg][j] = 0ULL;

  float4 pa, pb[8];
  auto loadA = [&](int k0) {
    int rr = tid >> 2, kq = (tid & 3) << 2;
    pa = __ldg((const float4*)(Ab + (size_t)rr * 1024 + k0 + kq));
  };
  auto loadB = [&](int k0) {
#pragma unroll
    for (int i = 0; i < 8; i++) {
      int f = tid + 256 * i;
      int rr = f >> 2, kq = (f & 3) << 2;
      pb[i] = __ldg((const float4*)(Bb + (size_t)rr * 1024 + k0 + kq));
    }
  };
  auto stage = [&](int s) {
    float* As = AsB + s * 16 * SRA;
    float* Bs = BsB + s * 16 * SRB;
    {
      int rr = tid >> 2, kq = (tid & 3) << 2;
      As[(kq + 0) * SRA + rr] = pa.x; As[(kq + 1) * SRA + rr] = pa.y;
      As[(kq + 2) * SRA + rr] = pa.z; As[(kq + 3) * SRA + rr] = pa.w;
    }
#pragma unroll
    for (int i = 0; i < 8; i++) {
      int f = tid + 256 * i;
      int rr = f >> 2, kq = (f & 3) << 2;
      Bs[(kq + 0) * SRB + rr] = pb[i].x; Bs[(kq + 1) * SRB + rr] = pb[i].y;
      Bs[(kq + 2) * SRB + rr] = pb[i].z; Bs[(kq + 3) * SRB + rr] = pb[i].w;
    }
  };

  loadA(0); loadB(0);
  stage(0);
  __syncthreads();

  int s = 0;
  for (int kt = 0; kt < 64; kt++) {
    if (kt + 1 < 64) { loadA((kt + 1) << 4); loadB((kt + 1) << 4); }
    const float* As = AsB + s * 16 * SRA;
    const float* Bs = BsB + s * 16 * SRB;
#pragma unroll
    for (int kk = 0; kk < 16; kk++) {
      const float* ar = As + kk * SRA + d0;
      ulonglong2 u0 = *(const ulonglong2*)ar;
      ulonglong2 u1 = *(const ulonglong2*)(ar + 4);
      ull ap[4] = {u0.x, u0.y, u1.x, u1.y};
      const float* br = Bs + kk * SRB + tx * 4;
#pragma unroll
      for (int cg = 0; cg < 4; cg++) {
        float4 bf = *(const float4*)(br + cg * 128);
        float bv[4] = {bf.x, bf.y, bf.z, bf.w};
#pragma unroll
        for (int j = 0; j < 4; j++) {
          ull bsp = splat2(bv[j]);
#pragma unroll
          for (int p = 0; p < 4; p++) fma2(acc[p][cg][j], ap[p], bsp);
        }
      }
    }
    if (kt + 1 < 64) {
      stage(s ^ 1);
      __syncthreads();
    }
    s ^= 1;
  }

  // epilogue: coalesced float4 along n into midT[b][g*64+d][n]
  const int b = bg >> 4, g = bg & 15;
  float* base = midT + ((size_t)b << 20) + ((size_t)(g * 64) << 10);
#pragma unroll
  for (int p = 0; p < 4; p++) {
    const int d = d0 + 2 * p;
#pragma unroll
    for (int cg = 0; cg < 4; cg++) {
      const int n0 = nb + cg * 128 + tx * 4;
      float lo[4], hi[4];
#pragma unroll
      for (int j = 0; j < 4; j++) { lo[j] = lo32(acc[p][cg][j]); hi[j] = hi32(acc[p][cg][j]); }
      *(float4*)(base + ((size_t)d << 10) + n0) = make_float4(lo[0], lo[1], lo[2], lo[3]);
      *(float4*)(base + ((size_t)(d + 1) << 10) + n0) = make_float4(hi[0], hi[1], hi[2], hi[3]);
    }
  }
}

// ---------------- fused mix1 + softmax + mix2 (FMA2) ----------------
__global__ __launch_bounds__(256) void fused_mix_softmax(
    const float* __restrict__ wl, const float* __restrict__ bl,
    const float* __restrict__ ww, const float* __restrict__ bw,
    const float* __restrict__ s, float* __restrict__ attn) {
  extern __shared__ float sm[];
  float* T = sm;
  float* wls  = sm + 16 * 1024;
  float* wwi  = wls + 256;
  float* bls  = wwi + 256;
  float* bws  = bls + 16;
  float* invs = bws + 16;
  const int n = blockIdx.x, b = blockIdx.y, tid = threadIdx.x;
  const int lane = tid & 31;
  wls[tid] = wl[tid];
  if (tid < 16) bls[tid] = bl[tid];
  __syncthreads();

  const float* sb = s + (((size_t)b * 16) << 20) + ((size_t)n << 10) + tid * 4;
  {
    ull sv[16][2];
#pragma unroll
    for (int h = 0; h < 16; h++) {
      float4 v = __ldg((const float4*)(sb + ((size_t)h << 20)));
      asm("mov.b64 %0, {%1,%2};" : "=l"(sv[h][0]) : "f"(v.x), "f"(v.y));
      asm("mov.b64 %0, {%1,%2};" : "=l"(sv[h][1]) : "f"(v.z), "f"(v.w));
    }
#pragma unroll
    for (int g = 0; g < 16; g++) {
      ull a0 = splat2(bls[g]), a1 = a0;
#pragma unroll
      for (int h = 0; h < 16; h++) {
        ull wsp = splat2(wls[g * 16 + h]);
        fma2(a0, wsp, sv[h][0]);
        fma2(a1, wsp, sv[h][1]);
      }
      *(float4*)&T[g * 1024 + tid * 4] = make_float4(lo32(a0), hi32(a0), lo32(a1), hi32(a1));
    }
  }
  __syncthreads();

  {
    const int g0 = (tid >> 5) * 2;
#pragma unroll
    for (int rr = 0; rr < 2; rr++) {
      float* row = &T[(g0 + rr) << 10];
      float v[32];
#pragma unroll
      for (int j = 0; j < 8; j++) {
        float4 x4 = *(const float4*)&row[lane * 4 + j * 128];
        v[j * 4 + 0] = x4.x; v[j * 4 + 1] = x4.y; v[j * 4 + 2] = x4.z; v[j * 4 + 3] = x4.w;
      }
      float mx = -1e30f;
#pragma unroll
      for (int i = 0; i < 32; i++) mx = fmaxf(mx, v[i]);
#pragma unroll
      for (int o = 16; o; o >>= 1) mx = fmaxf(mx, __shfl_xor_sync(0xffffffffu, mx, o));
      float sum = 0.f;
#pragma unroll
      for (int i = 0; i < 32; i++) { v[i] = __expf(v[i] - mx); sum += v[i]; }
#pragma unroll
      for (int o = 16; o; o >>= 1) sum += __shfl_xor_sync(0xffffffffu, sum, o);
#pragma unroll
      for (int j = 0; j < 8; j++)
        *(float4*)&row[lane * 4 + j * 128] =
            make_float4(v[j * 4 + 0], v[j * 4 + 1], v[j * 4 + 2], v[j * 4 + 3]);
      if (lane == 0) invs[g0 + rr] = 1.0f / sum;
    }
  }
  __syncthreads();
  wwi[tid] = ww[tid] * invs[tid & 15];
  if (tid < 16) bws[tid] = bw[tid];
  __syncthreads();

  float* ab = attn + (((size_t)b * 16) << 20) + ((size_t)n << 10) + tid * 4;
  {
    ull ev[16][2];
#pragma unroll
    for (int h = 0; h < 16; h++) {
      ulonglong2 u = *(const ulonglong2*)&T[h * 1024 + tid * 4];
      ev[h][0] = u.x; ev[h][1] = u.y;
    }
#pragma unroll
    for (int g = 0; g < 16; g++) {
      ull a0 = splat2(bws[g]), a1 = a0;
#pragma unroll
      for (int h = 0; h < 16; h++) {
        ull wsp = splat2(wwi[g * 16 + h]);
        fma2(a0, wsp, ev[h][0]);
        fma2(a1, wsp, ev[h][1]);
      }
      *(float4*)(ab + ((size_t)g << 20)) = make_float4(lo32(a0), hi32(a0), lo32(a1), hi32(a1));
    }
  }
}

// ---------------- launch ----------------
extern "C" void kernel_launch(void* const* d_in, const int* in_sizes, int n_in,
                              void* d_out, int out_size) {
  const float* x      = (const float*)d_in[0];
  const float* qkv_w  = (const float*)d_in[1];
  const float* qkv_b  = (const float*)d_in[2];
  const float* proj_w = (const float*)d_in[3];
  const float* proj_b = (const float*)d_in[4];
  const float* wl     = (const float*)d_in[5];
  const float* bl     = (const float*)d_in[6];
  const float* ww     = (const float*)d_in[7];
  const float* bw     = (const float*)d_in[8];
  float* out = (float*)d_out;
  float* attn = out + (size_t)BB * NN * CC;

  float* scratch = nullptr;
  cudaGetSymbolAddress((void**)&scratch, g_scratch);
  float* q    = scratch + OFF_Q;
  float* k    = scratch + OFF_K;
  float* vT   = scratch + OFF_VT;
  float* midT = scratch + OFF_MID;
  float* s    = scratch + OFF_S;

  const int SMEM_G  = 2 * (16 * 260 + 16 * 132) * 4;   // 50176
  const int SMEM_AV = 2 * (16 * 68 + 16 * 516) * 4;    // 74752
  const int FUSED_SMEM = (16 * 1024 + 256 + 256 + 16 + 16 + 16) * 4;
  static int smem_set = 0;
  if (!smem_set) {
    cudaFuncSetAttribute(g3_gemm<1, 0>, cudaFuncAttributeMaxDynamicSharedMemorySize, SMEM_G);
    cudaFuncSetAttribute(g3_gemm<0, 0>, cudaFuncAttributeMaxDynamicSharedMemorySize, SMEM_G);
    cudaFuncSetAttribute(g3_gemm<3, 1>, cudaFuncAttributeMaxDynamicSharedMemorySize, SMEM_G);
    cudaFuncSetAttribute(g3_av, cudaFuncAttributeMaxDynamicSharedMemorySize, SMEM_AV);
    cudaFuncSetAttribute(fused_mix_softmax, cudaFuncAttributeMaxDynamicSharedMemorySize, FUSED_SMEM);
    smem_set = 1;
  }

  // 1) qkv = x @ qkv_w^T + b -> q(*0.125), k, vT
  g3_gemm<1, 0><<<dim3(24, 16, 1), 256, SMEM_G>>>(
      x, qkv_w, CC, CC, CC, 0, 0, qkv_b, q, k, vT, 0, 0);
  // 2) s[b,h] = q[b,h] @ k[b,h]^T  (64 batches, K=64)
  g3_gemm<0, 0><<<dim3(8, 4, 64), 256, SMEM_G>>>(
      q, k, HDIM, HDIM, HDIM, (size_t)NN * HDIM, (size_t)NN * HDIM, nullptr,
      s, nullptr, nullptr, NN, (size_t)NN * NN);
  // 3) fused pre-mix + softmax + post-mix -> final attn
  fused_mix_softmax<<<dim3(NN, BB), 256, FUSED_SMEM>>>(wl, bl, ww, bw, s, attn);
  // 4) midT[b][c][n] = vT @ attn^T  (64 batches)
  g3_av<<<dim3(2, 1, 64), 256, SMEM_AV>>>(attn, vT, midT);
  // 5) out = midT^T @ proj_w^T + proj_b
  g3_gemm<3, 1><<<dim3(8, 16, 1), 256, SMEM_G>>>(
      midT, proj_w, 0, CC, CC, 0, 0, proj_b, out, nullptr, nullptr, CC, 0);
}